// round 13
// baseline (speedup 1.0000x reference)
#include <cuda_runtime.h>

#define Bn 4
#define Ln 200
#define Hn 256
#define NHn 4
#define HSn 64
#define Mrows (Bn * Ln)        // 800

__device__ float4 g_Q4 [Bn * Ln * (Hn / 4)];
__device__ float4 g_Kc4[Bn * Ln * (Hn / 4)];
__device__ float4 g_Vc4[Bn * Ln * (Hn / 4)];

typedef unsigned long long ull;

__device__ __forceinline__ void fma2(ull& acc, ull a, ull b)
{
    asm("fma.rn.f32x2 %0, %1, %2, %0;" : "+l"(acc) : "l"(a), "l"(b));
}
__device__ __forceinline__ ull packdup(float a)
{
    ull r;
    asm("mov.b64 %0, {%1, %1};" : "=l"(r) : "f"(a));
    return r;
}

// ---------------------------------------------------------------------------
// Strip projection GEMM v4 (R11 exact; proj region ~14us).
// ---------------------------------------------------------------------------
#define WPITCH 260
#define XROWS 20
#define XP 20
#define SBUF_BYTES (3200 + 2 * 16 * WPITCH * 4)

__global__ __launch_bounds__(512)
void proj_strip(const float4* __restrict__ queries,
                const float4* __restrict__ keys,
                const float4* __restrict__ apK4,
                const float4* __restrict__ apV4,
                const float4* __restrict__ Qw4, const float* __restrict__ Qb,
                const float4* __restrict__ Kw4, const float* __restrict__ Kb,
                const float4* __restrict__ Vw4, const float* __restrict__ Vb)
{
    __shared__ alignas(16) char sbuf[SBUF_BYTES];
    float* xs = reinterpret_cast<float*>(sbuf);
    float* ws = reinterpret_cast<float*>(sbuf + 3200);

    const int bx = blockIdx.x;
    const int z  = (bx < 49) ? 0 : (bx < 98) ? 1 : 2;
    const int li = bx - ((z == 0) ? 0 : (z == 1) ? 49 : 98);
    const int nC = (z == 2) ? 50 : 49;

    const int r0  = (Mrows * li) / nC;
    const int r1  = (Mrows * (li + 1)) / nC;
    const int cnt = r1 - r0;

    const float4* __restrict__ X  = (z == 0) ? queries : keys;
    const float4* __restrict__ W  = (z == 0) ? Qw4 : (z == 1) ? Kw4 : Vw4;
    const float*  __restrict__ Bv = (z == 0) ? Qb : (z == 1) ? Kb : Vb;

    const int t  = threadIdx.x;
    const int kh = t >> 8;
    const int tl = t & 255;
    const int tx = tl & 63;
    const int ty = tl >> 6;
    const int kb4 = kh * 32;

    int rowIdx[5];
    #pragma unroll
    for (int j = 0; j < 5; ++j) {
        int rr = ty + 4 * j;
        rowIdx[j] = (rr < cnt) ? rr : (cnt - 1);
    }

    ull acc01[5], acc23[5];
    #pragma unroll
    for (int j = 0; j < 5; ++j) { acc01[j] = 0ULL; acc23[j] = 0ULL; }

    const bool doX = (tl < 4 * cnt);
    const int  xrow = tl >> 2, xq = tl & 3;
    int wcol[4], wq[4];
    #pragma unroll
    for (int u = 0; u < 4; ++u) {
        const int e = tl + 256 * u;
        wcol[u] = e >> 2;
        wq[u]   = e & 3;
    }

    float4 xr = make_float4(0.f, 0.f, 0.f, 0.f);
    if (doX) xr = X[(r0 + xrow) * 64 + kb4 + xq];
    float4 wr[4];
    #pragma unroll
    for (int u = 0; u < 4; ++u) wr[u] = W[wcol[u] * 64 + kb4 + wq[u]];

    float* xsh = xs + kh * XROWS * XP;
    float* wsh = ws + kh * 16 * WPITCH;

    for (int c = 0; c < 8; ++c) {
        if (doX)
            *reinterpret_cast<float4*>(&xsh[xrow * XP + xq * 4]) = xr;
        #pragma unroll
        for (int u = 0; u < 4; ++u) {
            wsh[(wq[u] * 4 + 0) * WPITCH + wcol[u]] = wr[u].x;
            wsh[(wq[u] * 4 + 1) * WPITCH + wcol[u]] = wr[u].y;
            wsh[(wq[u] * 4 + 2) * WPITCH + wcol[u]] = wr[u].z;
            wsh[(wq[u] * 4 + 3) * WPITCH + wcol[u]] = wr[u].w;
        }
        __syncthreads();

        if (c + 1 < 8) {
            const int kq = kb4 + (c + 1) * 4;
            if (doX) xr = X[(r0 + xrow) * 64 + kq + xq];
            #pragma unroll
            for (int u = 0; u < 4; ++u) wr[u] = W[wcol[u] * 64 + kq + wq[u]];
        }

        #pragma unroll
        for (int g = 0; g < 4; ++g) {
            float4 xv[5];
            #pragma unroll
            for (int j = 0; j < 5; ++j)
                xv[j] = *reinterpret_cast<const float4*>(&xsh[rowIdx[j] * XP + g * 4]);
            #pragma unroll
            for (int i = 0; i < 4; ++i) {
                const int kk = g * 4 + i;
                const ulonglong2 wp =
                    *reinterpret_cast<const ulonglong2*>(&wsh[kk * WPITCH + tx * 4]);
                #pragma unroll
                for (int j = 0; j < 5; ++j) {
                    const float a = (i == 0) ? xv[j].x : (i == 1) ? xv[j].y
                                  : (i == 2) ? xv[j].z : xv[j].w;
                    const ull aa = packdup(a);
                    fma2(acc01[j], aa, wp.x);
                    fma2(acc23[j], aa, wp.y);
                }
            }
        }
        __syncthreads();
    }

    ull* red = reinterpret_cast<ull*>(sbuf + 3200);
    if (kh == 1) {
        #pragma unroll
        for (int j = 0; j < 5; ++j) {
            red[(j * 2 + 0) * 256 + tl] = acc01[j];
            red[(j * 2 + 1) * 256 + tl] = acc23[j];
        }
    }
    __syncthreads();

    if (kh == 0) {
        const float4 bias = reinterpret_cast<const float4*>(Bv)[tx];
        float4* __restrict__ dst = (z == 0) ? g_Q4 : (z == 1) ? g_Kc4 : g_Vc4;
        const float4* __restrict__ ap = (z == 1) ? apK4 : apV4;

        #pragma unroll
        for (int j = 0; j < 5; ++j) {
            const int rr = ty + 4 * j;
            if (rr < cnt) {
                const int row = r0 + rr;
                const float2 p01 = *reinterpret_cast<const float2*>(&red[(j * 2 + 0) * 256 + tl]);
                const float2 p23 = *reinterpret_cast<const float2*>(&red[(j * 2 + 1) * 256 + tl]);
                const float2 c01 = *reinterpret_cast<float2*>(&acc01[j]);
                const float2 c23 = *reinterpret_cast<float2*>(&acc23[j]);
                float4 o;
                o.x = c01.x + p01.x + bias.x;
                o.y = c01.y + p01.y + bias.y;
                o.z = c23.x + p23.x + bias.z;
                o.w = c23.y + p23.y + bias.w;
                if (z != 0) {
                    const float4 pa = ap[row * 64 + tx];
                    o.x += pa.x; o.y += pa.y; o.z += pa.z; o.w += pa.w;
                }
                dst[row * 64 + tx] = o;
            }
        }
    }
}

// ---------------------------------------------------------------------------
// Attention v2: FUSED single-pass with online softmax.
// One streaming loop per row reads tK,dK,Kc (logit) and tV,dV,Vc (value)
// per key-row; running max/sum with rescaled accumulator per (msub, head)
// subset; log-sum-exp combine across the 8 msub subsets at the end.
// No sW, no mid-kernel softmax phase — memory streams continuously.
// ---------------------------------------------------------------------------
__global__ __launch_bounds__(512)
void attn_kernel(const float4* __restrict__ tK, const float4* __restrict__ tV,
                 const float4* __restrict__ dK, const float4* __restrict__ dV,
                 const unsigned char* __restrict__ time_mask,
                 float4* __restrict__ out)
{
    const int bx = blockIdx.x;               // 0..399
    const int b  = bx & (Bn - 1);
    const int p  = bx >> 2;                  // 0..99
    const int t    = threadIdx.x;
    const int msub = t >> 6;                 // 0..7
    const int qd   = t & 63;
    const int head = qd >> 4;

    __shared__ float4 sRed[8][64];
    __shared__ float2 sMS[8][NHn];           // (running max, running sum) per msub/head
    __shared__ float  qsh[Hn];

    const float4* __restrict__ Kc4 = g_Kc4;
    const float4* __restrict__ Vc4 = g_Vc4;
    const float*  __restrict__ gQ  = (const float*)g_Q4;

    asm volatile("griddepcontrol.wait;" ::: "memory");

    #pragma unroll 1
    for (int rr = 0; rr < 2; ++rr) {
        const int l = rr ? p : (Ln - 1 - p);   // heavy row first

        if (t < Hn) qsh[t] = gQ[(size_t)(b * Ln + l) * Hn + t];
        __syncthreads();
        const float4 qv = *reinterpret_cast<const float4*>(&qsh[qd * 4]);

        const bool tm   = time_mask[b * Ln + l] != 0;
        const int  mEnd = tm ? Ln : (l + 1);
        const size_t rowBase = ((size_t)(b * Ln + l)) * Ln;

        float4 acc = make_float4(0.f, 0.f, 0.f, 0.f);
        float  mx  = -1e30f;
        float  sum = 0.f;

        #pragma unroll 2
        for (int m0 = 0; m0 < mEnd; m0 += 8) {
            const int m = m0 + msub;
            if (m < mEnd) {
                const size_t off  = (rowBase + (size_t)m) * 64 + qd;
                const size_t koff = (size_t)(b * Ln + m) * 64 + qd;
                // value-side loads issue first (independent of logit chain)
                const float4 x = tV[off];
                const float4 y = dV[off];
                const float4 v = Vc4[koff];

                float s = 0.f;
                if (!tm) {
                    const float4 a = tK[off];
                    const float4 c = dK[off];
                    const float4 k = Kc4[koff];
                    s = qv.x * (a.x + c.x + k.x) + qv.y * (a.y + c.y + k.y)
                      + qv.z * (a.z + c.z + k.z) + qv.w * (a.w + c.w + k.w);
                    s += __shfl_xor_sync(0xffffffffu, s, 8);
                    s += __shfl_xor_sync(0xffffffffu, s, 4);
                    s += __shfl_xor_sync(0xffffffffu, s, 2);
                    s += __shfl_xor_sync(0xffffffffu, s, 1);
                    s *= 0.125f;                       // 1/sqrt(64)
                }
                // online softmax update (identical across the 16-lane group)
                const float mxn = fmaxf(mx, s);
                const float sc  = __expf(mx - mxn);    // 0 on first valid iter
                const float w   = __expf(s - mxn);
                sum = sum * sc + w;
                acc.x = acc.x * sc + w * (x.x + y.x + v.x);
                acc.y = acc.y * sc + w * (x.y + y.y + v.y);
                acc.z = acc.z * sc + w * (x.z + y.z + v.z);
                acc.w = acc.w * sc + w * (x.w + y.w + v.w);
                mx = mxn;
            }
        }

        sRed[msub][qd] = acc;
        if ((qd & 15) == 0) sMS[msub][head] = make_float2(mx, sum);
        __syncthreads();

        // log-sum-exp combine across the 8 msub subsets (msub 0, 64 threads)
        if (msub == 0) {
            float MX = -1e30f;
            float2 ms[8];
            #pragma unroll
            for (int r = 0; r < 8; ++r) {
                ms[r] = sMS[r][head];
                MX = fmaxf(MX, ms[r].x);
            }
            float T = 0.f;
            float4 o = make_float4(0.f, 0.f, 0.f, 0.f);
            #pragma unroll
            for (int r = 0; r < 8; ++r) {
                const float sc = __expf(ms[r].x - MX);
                T += ms[r].y * sc;
                const float4 rv = sRed[r][qd];
                o.x += rv.x * sc; o.y += rv.y * sc;
                o.z += rv.z * sc; o.w += rv.w * sc;
            }
            const float inv = 1.f / T;
            o.x *= inv; o.y *= inv; o.z *= inv; o.w *= inv;
            out[(size_t)(b * Ln + l) * 64 + qd] = o;
        }
        __syncthreads();
    }
}

// ---------------------------------------------------------------------------
extern "C" void kernel_launch(void* const* d_in, const int* in_sizes, int n_in,
                              void* d_out, int out_size)
{
    const float4* queries = (const float4*)d_in[0];
    const float4* keys    = (const float4*)d_in[1];
    const float4* tK      = (const float4*)d_in[2];
    const float4* tV      = (const float4*)d_in[3];
    const float4* dK      = (const float4*)d_in[4];
    const float4* dV      = (const float4*)d_in[5];
    const float4* apK     = (const float4*)d_in[6];
    const float4* apV     = (const float4*)d_in[7];
    const float4* Qw      = (const float4*)d_in[8];
    const float* Qb       = (const float*)d_in[9];
    const float4* Kw      = (const float4*)d_in[10];
    const float* Kb       = (const float*)d_in[11];
    const float4* Vw      = (const float4*)d_in[12];
    const float* Vb       = (const float*)d_in[13];
    const unsigned char* time_mask = (const unsigned char*)d_in[14];

    proj_strip<<<148, 512>>>(queries, keys, apK, apV,
                             Qw, Qb, Kw, Kb, Vw, Vb);

    cudaLaunchConfig_t cfg = {};
    cfg.gridDim  = dim3((Bn * Ln) / 2, 1, 1);
    cfg.blockDim = dim3(512, 1, 1);
    cfg.dynamicSmemBytes = 0;
    cfg.stream = 0;
    cudaLaunchAttribute attrs[1];
    attrs[0].id = cudaLaunchAttributeProgrammaticStreamSerialization;
    attrs[0].val.programmaticStreamSerializationAllowed = 1;
    cfg.attrs = attrs;
    cfg.numAttrs = 1;
    cudaLaunchKernelEx(&cfg, attn_kernel, tK, tV, dK, dV, time_mask,
                       (float4*)d_out);
}

// round 14
// speedup vs baseline: 1.0993x; 1.0993x over previous
#include <cuda_runtime.h>

#define Bn 4
#define Ln 200
#define Hn 256
#define NHn 4
#define HSn 64
#define Mrows (Bn * Ln)        // 800

__device__ float4 g_Q4 [Bn * Ln * (Hn / 4)];
__device__ float4 g_Kc4[Bn * Ln * (Hn / 4)];
__device__ float4 g_Vc4[Bn * Ln * (Hn / 4)];

typedef unsigned long long ull;

__device__ __forceinline__ void fma2(ull& acc, ull a, ull b)
{
    asm("fma.rn.f32x2 %0, %1, %2, %0;" : "+l"(acc) : "l"(a), "l"(b));
}
__device__ __forceinline__ ull packdup(float a)
{
    ull r;
    asm("mov.b64 %0, {%1, %1};" : "=l"(r) : "f"(a));
    return r;
}

// ---------------------------------------------------------------------------
// Strip projection GEMM v4 (R11 exact; proj region ~14us).
// ---------------------------------------------------------------------------
#define WPITCH 260
#define XROWS 20
#define XP 20
#define SBUF_BYTES (3200 + 2 * 16 * WPITCH * 4)

__global__ __launch_bounds__(512)
void proj_strip(const float4* __restrict__ queries,
                const float4* __restrict__ keys,
                const float4* __restrict__ apK4,
                const float4* __restrict__ apV4,
                const float4* __restrict__ Qw4, const float* __restrict__ Qb,
                const float4* __restrict__ Kw4, const float* __restrict__ Kb,
                const float4* __restrict__ Vw4, const float* __restrict__ Vb)
{
    __shared__ alignas(16) char sbuf[SBUF_BYTES];
    float* xs = reinterpret_cast<float*>(sbuf);
    float* ws = reinterpret_cast<float*>(sbuf + 3200);

    const int bx = blockIdx.x;
    const int z  = (bx < 49) ? 0 : (bx < 98) ? 1 : 2;
    const int li = bx - ((z == 0) ? 0 : (z == 1) ? 49 : 98);
    const int nC = (z == 2) ? 50 : 49;

    const int r0  = (Mrows * li) / nC;
    const int r1  = (Mrows * (li + 1)) / nC;
    const int cnt = r1 - r0;

    const float4* __restrict__ X  = (z == 0) ? queries : keys;
    const float4* __restrict__ W  = (z == 0) ? Qw4 : (z == 1) ? Kw4 : Vw4;
    const float*  __restrict__ Bv = (z == 0) ? Qb : (z == 1) ? Kb : Vb;

    const int t  = threadIdx.x;
    const int kh = t >> 8;
    const int tl = t & 255;
    const int tx = tl & 63;
    const int ty = tl >> 6;
    const int kb4 = kh * 32;

    int rowIdx[5];
    #pragma unroll
    for (int j = 0; j < 5; ++j) {
        int rr = ty + 4 * j;
        rowIdx[j] = (rr < cnt) ? rr : (cnt - 1);
    }

    ull acc01[5], acc23[5];
    #pragma unroll
    for (int j = 0; j < 5; ++j) { acc01[j] = 0ULL; acc23[j] = 0ULL; }

    const bool doX = (tl < 4 * cnt);
    const int  xrow = tl >> 2, xq = tl & 3;
    int wcol[4], wq[4];
    #pragma unroll
    for (int u = 0; u < 4; ++u) {
        const int e = tl + 256 * u;
        wcol[u] = e >> 2;
        wq[u]   = e & 3;
    }

    float4 xr = make_float4(0.f, 0.f, 0.f, 0.f);
    if (doX) xr = X[(r0 + xrow) * 64 + kb4 + xq];
    float4 wr[4];
    #pragma unroll
    for (int u = 0; u < 4; ++u) wr[u] = W[wcol[u] * 64 + kb4 + wq[u]];

    float* xsh = xs + kh * XROWS * XP;
    float* wsh = ws + kh * 16 * WPITCH;

    for (int c = 0; c < 8; ++c) {
        if (doX)
            *reinterpret_cast<float4*>(&xsh[xrow * XP + xq * 4]) = xr;
        #pragma unroll
        for (int u = 0; u < 4; ++u) {
            wsh[(wq[u] * 4 + 0) * WPITCH + wcol[u]] = wr[u].x;
            wsh[(wq[u] * 4 + 1) * WPITCH + wcol[u]] = wr[u].y;
            wsh[(wq[u] * 4 + 2) * WPITCH + wcol[u]] = wr[u].z;
            wsh[(wq[u] * 4 + 3) * WPITCH + wcol[u]] = wr[u].w;
        }
        __syncthreads();

        if (c + 1 < 8) {
            const int kq = kb4 + (c + 1) * 4;
            if (doX) xr = X[(r0 + xrow) * 64 + kq + xq];
            #pragma unroll
            for (int u = 0; u < 4; ++u) wr[u] = W[wcol[u] * 64 + kq + wq[u]];
        }

        #pragma unroll
        for (int g = 0; g < 4; ++g) {
            float4 xv[5];
            #pragma unroll
            for (int j = 0; j < 5; ++j)
                xv[j] = *reinterpret_cast<const float4*>(&xsh[rowIdx[j] * XP + g * 4]);
            #pragma unroll
            for (int i = 0; i < 4; ++i) {
                const int kk = g * 4 + i;
                const ulonglong2 wp =
                    *reinterpret_cast<const ulonglong2*>(&wsh[kk * WPITCH + tx * 4]);
                #pragma unroll
                for (int j = 0; j < 5; ++j) {
                    const float a = (i == 0) ? xv[j].x : (i == 1) ? xv[j].y
                                  : (i == 2) ? xv[j].z : xv[j].w;
                    const ull aa = packdup(a);
                    fma2(acc01[j], aa, wp.x);
                    fma2(acc23[j], aa, wp.y);
                }
            }
        }
        __syncthreads();
    }

    ull* red = reinterpret_cast<ull*>(sbuf + 3200);
    if (kh == 1) {
        #pragma unroll
        for (int j = 0; j < 5; ++j) {
            red[(j * 2 + 0) * 256 + tl] = acc01[j];
            red[(j * 2 + 1) * 256 + tl] = acc23[j];
        }
    }
    __syncthreads();

    if (kh == 0) {
        const float4 bias = reinterpret_cast<const float4*>(Bv)[tx];
        float4* __restrict__ dst = (z == 0) ? g_Q4 : (z == 1) ? g_Kc4 : g_Vc4;
        const float4* __restrict__ ap = (z == 1) ? apK4 : apV4;

        #pragma unroll
        for (int j = 0; j < 5; ++j) {
            const int rr = ty + 4 * j;
            if (rr < cnt) {
                const int row = r0 + rr;
                const float2 p01 = *reinterpret_cast<const float2*>(&red[(j * 2 + 0) * 256 + tl]);
                const float2 p23 = *reinterpret_cast<const float2*>(&red[(j * 2 + 1) * 256 + tl]);
                const float2 c01 = *reinterpret_cast<float2*>(&acc01[j]);
                const float2 c23 = *reinterpret_cast<float2*>(&acc23[j]);
                float4 o;
                o.x = c01.x + p01.x + bias.x;
                o.y = c01.y + p01.y + bias.y;
                o.z = c23.x + p23.x + bias.z;
                o.w = c23.y + p23.y + bias.w;
                if (z != 0) {
                    const float4 pa = ap[row * 64 + tx];
                    o.x += pa.x; o.y += pa.y; o.z += pa.z; o.w += pa.w;
                }
                dst[row * 64 + tx] = o;
            }
        }
    }
}

// ---------------------------------------------------------------------------
// Attention (R7 core, unroll 3, reg-capped at 3 CTAs/SM).
// One CTA per (b, row-pair), 512 threads = 8 key-rows x 64 float4 lanes.
// ---------------------------------------------------------------------------
__global__ __launch_bounds__(512, 3)
void attn_kernel(const float4* __restrict__ tK, const float4* __restrict__ tV,
                 const float4* __restrict__ dK, const float4* __restrict__ dV,
                 const unsigned char* __restrict__ time_mask,
                 float4* __restrict__ out)
{
    const int bx = blockIdx.x;               // 0..399
    const int b  = bx & (Bn - 1);
    const int p  = bx >> 2;                  // 0..99
    const int t    = threadIdx.x;
    const int msub = t >> 6;                 // 0..7
    const int qd   = t & 63;
    const int head = qd >> 4;

    __shared__ float  sW[NHn][Ln];
    __shared__ float4 sRed[8][64];
    __shared__ float  qsh[Hn];

    const float4* __restrict__ Kc4 = g_Kc4;
    const float4* __restrict__ Vc4 = g_Vc4;
    const float*  __restrict__ gQ  = (const float*)g_Q4;

    asm volatile("griddepcontrol.wait;" ::: "memory");

    #pragma unroll 1
    for (int rr = 0; rr < 2; ++rr) {
        const int l = rr ? p : (Ln - 1 - p);   // heavy row first

        if (t < Hn) qsh[t] = gQ[(size_t)(b * Ln + l) * Hn + t];
        __syncthreads();
        const float4 qv = *reinterpret_cast<const float4*>(&qsh[qd * 4]);

        const bool tm   = time_mask[b * Ln + l] != 0;
        const int  mEnd = tm ? Ln : (l + 1);
        const size_t rowBase = ((size_t)(b * Ln + l)) * Ln;

        if (!tm) {
            #pragma unroll 3
            for (int m0 = 0; m0 < mEnd; m0 += 8) {
                const int m = m0 + msub;
                float s = 0.f;
                if (m < mEnd) {
                    const size_t off = (rowBase + (size_t)m) * 64 + qd;
                    const float4 a = tK[off];
                    const float4 c = dK[off];
                    const float4 k = Kc4[(size_t)(b * Ln + m) * 64 + qd];
                    s = qv.x * (a.x + c.x + k.x) + qv.y * (a.y + c.y + k.y)
                      + qv.z * (a.z + c.z + k.z) + qv.w * (a.w + c.w + k.w);
                }
                s += __shfl_xor_sync(0xffffffffu, s, 8);
                s += __shfl_xor_sync(0xffffffffu, s, 4);
                s += __shfl_xor_sync(0xffffffffu, s, 2);
                s += __shfl_xor_sync(0xffffffffu, s, 1);
                if (m < mEnd && (qd & 15) == 0)
                    sW[head][m] = s;
            }
            __syncthreads();

            if (t < 128) {
                const int h    = t >> 5;
                const int lane = t & 31;
                float mx = -3.4e38f;
                for (int m = lane; m < mEnd; m += 32) mx = fmaxf(mx, sW[h][m]);
                #pragma unroll
                for (int o = 16; o; o >>= 1) mx = fmaxf(mx, __shfl_xor_sync(0xffffffffu, mx, o));
                float sum = 0.f;
                for (int m = lane; m < mEnd; m += 32) {
                    const float e = __expf(0.125f * (sW[h][m] - mx));  // 1/sqrt(64)
                    sW[h][m] = e;
                    sum += e;
                }
                #pragma unroll
                for (int o = 16; o; o >>= 1) sum += __shfl_xor_sync(0xffffffffu, sum, o);
                const float inv = 1.f / sum;
                for (int m = lane; m < mEnd; m += 32) sW[h][m] *= inv;
            }
        } else {
            const float u = 1.f / (float)Ln;
            for (int m = t; m < Ln; m += 512) {
                sW[0][m] = u; sW[1][m] = u; sW[2][m] = u; sW[3][m] = u;
            }
        }
        __syncthreads();

        float4 acc = make_float4(0.f, 0.f, 0.f, 0.f);
        #pragma unroll 3
        for (int m0 = 0; m0 < mEnd; m0 += 8) {
            const int m = m0 + msub;
            if (m < mEnd) {
                const float  a   = sW[head][m];
                const size_t off = (rowBase + (size_t)m) * 64 + qd;
                const float4 x = tV[off];
                const float4 y = dV[off];
                const float4 v = Vc4[(size_t)(b * Ln + m) * 64 + qd];
                acc.x += a * (x.x + y.x + v.x);
                acc.y += a * (x.y + y.y + v.y);
                acc.z += a * (x.z + y.z + v.z);
                acc.w += a * (x.w + y.w + v.w);
            }
        }
        sRed[msub][qd] = acc;
        __syncthreads();
        if (msub == 0) {
            float4 o = sRed[0][qd];
            #pragma unroll
            for (int r = 1; r < 8; ++r) {
                const float4 rv = sRed[r][qd];
                o.x += rv.x; o.y += rv.y; o.z += rv.z; o.w += rv.w;
            }
            out[(size_t)(b * Ln + l) * 64 + qd] = o;
        }
        __syncthreads();
    }
}

// ---------------------------------------------------------------------------
extern "C" void kernel_launch(void* const* d_in, const int* in_sizes, int n_in,
                              void* d_out, int out_size)
{
    const float4* queries = (const float4*)d_in[0];
    const float4* keys    = (const float4*)d_in[1];
    const float4* tK      = (const float4*)d_in[2];
    const float4* tV      = (const float4*)d_in[3];
    const float4* dK      = (const float4*)d_in[4];
    const float4* dV      = (const float4*)d_in[5];
    const float4* apK     = (const float4*)d_in[6];
    const float4* apV     = (const float4*)d_in[7];
    const float4* Qw      = (const float4*)d_in[8];
    const float* Qb       = (const float*)d_in[9];
    const float4* Kw      = (const float4*)d_in[10];
    const float* Kb       = (const float*)d_in[11];
    const float4* Vw      = (const float4*)d_in[12];
    const float* Vb       = (const float*)d_in[13];
    const unsigned char* time_mask = (const unsigned char*)d_in[14];

    proj_strip<<<148, 512>>>(queries, keys, apK, apV,
                             Qw, Qb, Kw, Kb, Vw, Vb);

    cudaLaunchConfig_t cfg = {};
    cfg.gridDim  = dim3((Bn * Ln) / 2, 1, 1);
    cfg.blockDim = dim3(512, 1, 1);
    cfg.dynamicSmemBytes = 0;
    cfg.stream = 0;
    cudaLaunchAttribute attrs[1];
    attrs[0].id = cudaLaunchAttributeProgrammaticStreamSerialization;
    attrs[0].val.programmaticStreamSerializationAllowed = 1;
    cfg.attrs = attrs;
    cfg.numAttrs = 1;
    cudaLaunchKernelEx(&cfg, attn_kernel, tK, tV, dK, dV, time_mask,
                       (float4*)d_out);
}

// round 15
// speedup vs baseline: 1.1559x; 1.0515x over previous
#include <cuda_runtime.h>

#define Bn 4
#define Ln 200
#define Hn 256
#define NHn 4
#define HSn 64
#define Mrows (Bn * Ln)        // 800

__device__ float4 g_Q4 [Bn * Ln * (Hn / 4)];
__device__ float4 g_Kc4[Bn * Ln * (Hn / 4)];
__device__ float4 g_Vc4[Bn * Ln * (Hn / 4)];

typedef unsigned long long ull;

__device__ __forceinline__ void fma2(ull& acc, ull a, ull b)
{
    asm("fma.rn.f32x2 %0, %1, %2, %0;" : "+l"(acc) : "l"(a), "l"(b));
}
__device__ __forceinline__ ull packdup(float a)
{
    ull r;
    asm("mov.b64 %0, {%1, %1};" : "=l"(r) : "f"(a));
    return r;
}

// ---------------------------------------------------------------------------
// Strip projection GEMM v4 (R11 exact; proj region ~14us).
// ---------------------------------------------------------------------------
#define WPITCH 260
#define XROWS 20
#define XP 20
#define SBUF_BYTES (3200 + 2 * 16 * WPITCH * 4)

__global__ __launch_bounds__(512)
void proj_strip(const float4* __restrict__ queries,
                const float4* __restrict__ keys,
                const float4* __restrict__ apK4,
                const float4* __restrict__ apV4,
                const float4* __restrict__ Qw4, const float* __restrict__ Qb,
                const float4* __restrict__ Kw4, const float* __restrict__ Kb,
                const float4* __restrict__ Vw4, const float* __restrict__ Vb)
{
    __shared__ alignas(16) char sbuf[SBUF_BYTES];
    float* xs = reinterpret_cast<float*>(sbuf);
    float* ws = reinterpret_cast<float*>(sbuf + 3200);

    const int bx = blockIdx.x;
    const int z  = (bx < 49) ? 0 : (bx < 98) ? 1 : 2;
    const int li = bx - ((z == 0) ? 0 : (z == 1) ? 49 : 98);
    const int nC = (z == 2) ? 50 : 49;

    const int r0  = (Mrows * li) / nC;
    const int r1  = (Mrows * (li + 1)) / nC;
    const int cnt = r1 - r0;

    const float4* __restrict__ X  = (z == 0) ? queries : keys;
    const float4* __restrict__ W  = (z == 0) ? Qw4 : (z == 1) ? Kw4 : Vw4;
    const float*  __restrict__ Bv = (z == 0) ? Qb : (z == 1) ? Kb : Vb;

    const int t  = threadIdx.x;
    const int kh = t >> 8;
    const int tl = t & 255;
    const int tx = tl & 63;
    const int ty = tl >> 6;
    const int kb4 = kh * 32;

    int rowIdx[5];
    #pragma unroll
    for (int j = 0; j < 5; ++j) {
        int rr = ty + 4 * j;
        rowIdx[j] = (rr < cnt) ? rr : (cnt - 1);
    }

    ull acc01[5], acc23[5];
    #pragma unroll
    for (int j = 0; j < 5; ++j) { acc01[j] = 0ULL; acc23[j] = 0ULL; }

    const bool doX = (tl < 4 * cnt);
    const int  xrow = tl >> 2, xq = tl & 3;
    int wcol[4], wq[4];
    #pragma unroll
    for (int u = 0; u < 4; ++u) {
        const int e = tl + 256 * u;
        wcol[u] = e >> 2;
        wq[u]   = e & 3;
    }

    float4 xr = make_float4(0.f, 0.f, 0.f, 0.f);
    if (doX) xr = X[(r0 + xrow) * 64 + kb4 + xq];
    float4 wr[4];
    #pragma unroll
    for (int u = 0; u < 4; ++u) wr[u] = W[wcol[u] * 64 + kb4 + wq[u]];

    float* xsh = xs + kh * XROWS * XP;
    float* wsh = ws + kh * 16 * WPITCH;

    for (int c = 0; c < 8; ++c) {
        if (doX)
            *reinterpret_cast<float4*>(&xsh[xrow * XP + xq * 4]) = xr;
        #pragma unroll
        for (int u = 0; u < 4; ++u) {
            wsh[(wq[u] * 4 + 0) * WPITCH + wcol[u]] = wr[u].x;
            wsh[(wq[u] * 4 + 1) * WPITCH + wcol[u]] = wr[u].y;
            wsh[(wq[u] * 4 + 2) * WPITCH + wcol[u]] = wr[u].z;
            wsh[(wq[u] * 4 + 3) * WPITCH + wcol[u]] = wr[u].w;
        }
        __syncthreads();

        if (c + 1 < 8) {
            const int kq = kb4 + (c + 1) * 4;
            if (doX) xr = X[(r0 + xrow) * 64 + kq + xq];
            #pragma unroll
            for (int u = 0; u < 4; ++u) wr[u] = W[wcol[u] * 64 + kq + wq[u]];
        }

        #pragma unroll
        for (int g = 0; g < 4; ++g) {
            float4 xv[5];
            #pragma unroll
            for (int j = 0; j < 5; ++j)
                xv[j] = *reinterpret_cast<const float4*>(&xsh[rowIdx[j] * XP + g * 4]);
            #pragma unroll
            for (int i = 0; i < 4; ++i) {
                const int kk = g * 4 + i;
                const ulonglong2 wp =
                    *reinterpret_cast<const ulonglong2*>(&wsh[kk * WPITCH + tx * 4]);
                #pragma unroll
                for (int j = 0; j < 5; ++j) {
                    const float a = (i == 0) ? xv[j].x : (i == 1) ? xv[j].y
                                  : (i == 2) ? xv[j].z : xv[j].w;
                    const ull aa = packdup(a);
                    fma2(acc01[j], aa, wp.x);
                    fma2(acc23[j], aa, wp.y);
                }
            }
        }
        __syncthreads();
    }

    ull* red = reinterpret_cast<ull*>(sbuf + 3200);
    if (kh == 1) {
        #pragma unroll
        for (int j = 0; j < 5; ++j) {
            red[(j * 2 + 0) * 256 + tl] = acc01[j];
            red[(j * 2 + 1) * 256 + tl] = acc23[j];
        }
    }
    __syncthreads();

    if (kh == 0) {
        const float4 bias = reinterpret_cast<const float4*>(Bv)[tx];
        float4* __restrict__ dst = (z == 0) ? g_Q4 : (z == 1) ? g_Kc4 : g_Vc4;
        const float4* __restrict__ ap = (z == 1) ? apK4 : apV4;

        #pragma unroll
        for (int j = 0; j < 5; ++j) {
            const int rr = ty + 4 * j;
            if (rr < cnt) {
                const int row = r0 + rr;
                const float2 p01 = *reinterpret_cast<const float2*>(&red[(j * 2 + 0) * 256 + tl]);
                const float2 p23 = *reinterpret_cast<const float2*>(&red[(j * 2 + 1) * 256 + tl]);
                const float2 c01 = *reinterpret_cast<float2*>(&acc01[j]);
                const float2 c23 = *reinterpret_cast<float2*>(&acc23[j]);
                float4 o;
                o.x = c01.x + p01.x + bias.x;
                o.y = c01.y + p01.y + bias.y;
                o.z = c23.x + p23.x + bias.z;
                o.w = c23.y + p23.y + bias.w;
                if (z != 0) {
                    const float4 pa = ap[row * 64 + tx];
                    o.x += pa.x; o.y += pa.y; o.z += pa.z; o.w += pa.w;
                }
                dst[row * 64 + tx] = o;
            }
        }
    }
}

// ---------------------------------------------------------------------------
// Attention v5: 444 = 3x148 cost-balanced CTAs (R7 row body, unroll 2).
// Tasks = 800 rows sorted by descending causal cost: task i -> l = 199-(i>>2),
// b = i&3. CTA c runs tasks {c, 887-c} (second valid iff >= 800 excluded):
// pair cost is the constant ~178 for c>87, single 178..200 for c<=87.
// Every SM hosts exactly 3 CTAs; per-SM work within +-2% of ideal.
// ---------------------------------------------------------------------------
__global__ __launch_bounds__(512, 3)
void attn_kernel(const float4* __restrict__ tK, const float4* __restrict__ tV,
                 const float4* __restrict__ dK, const float4* __restrict__ dV,
                 const unsigned char* __restrict__ time_mask,
                 float4* __restrict__ out)
{
    const int c    = blockIdx.x;             // 0..443
    const int t    = threadIdx.x;
    const int msub = t >> 6;                 // 0..7
    const int qd   = t & 63;
    const int head = qd >> 4;

    __shared__ float  sW[NHn][Ln];
    __shared__ float4 sRed[8][64];
    __shared__ float  qsh[Hn];

    const float4* __restrict__ Kc4 = g_Kc4;
    const float4* __restrict__ Vc4 = g_Vc4;
    const float*  __restrict__ gQ  = (const float*)g_Q4;

    asm volatile("griddepcontrol.wait;" ::: "memory");

    #pragma unroll 1
    for (int ti = 0; ti < 2; ++ti) {
        const int i = (ti == 0) ? c : (887 - c);
        if (i >= Mrows) continue;            // uniform across CTA
        const int l = (Ln - 1) - (i >> 2);
        const int b = i & 3;

        if (t < Hn) qsh[t] = gQ[(size_t)(b * Ln + l) * Hn + t];
        __syncthreads();
        const float4 qv = *reinterpret_cast<const float4*>(&qsh[qd * 4]);

        const bool tm   = time_mask[b * Ln + l] != 0;
        const int  mEnd = tm ? Ln : (l + 1);
        const size_t rowBase = ((size_t)(b * Ln + l)) * Ln;

        if (!tm) {
            #pragma unroll 2
            for (int m0 = 0; m0 < mEnd; m0 += 8) {
                const int m = m0 + msub;
                float s = 0.f;
                if (m < mEnd) {
                    const size_t off = (rowBase + (size_t)m) * 64 + qd;
                    const float4 a = tK[off];
                    const float4 cc = dK[off];
                    const float4 k = Kc4[(size_t)(b * Ln + m) * 64 + qd];
                    s = qv.x * (a.x + cc.x + k.x) + qv.y * (a.y + cc.y + k.y)
                      + qv.z * (a.z + cc.z + k.z) + qv.w * (a.w + cc.w + k.w);
                }
                s += __shfl_xor_sync(0xffffffffu, s, 8);
                s += __shfl_xor_sync(0xffffffffu, s, 4);
                s += __shfl_xor_sync(0xffffffffu, s, 2);
                s += __shfl_xor_sync(0xffffffffu, s, 1);
                if (m < mEnd && (qd & 15) == 0)
                    sW[head][m] = s;
            }
            __syncthreads();

            if (t < 128) {
                const int h    = t >> 5;
                const int lane = t & 31;
                float mx = -3.4e38f;
                for (int m = lane; m < mEnd; m += 32) mx = fmaxf(mx, sW[h][m]);
                #pragma unroll
                for (int o = 16; o; o >>= 1) mx = fmaxf(mx, __shfl_xor_sync(0xffffffffu, mx, o));
                float sum = 0.f;
                for (int m = lane; m < mEnd; m += 32) {
                    const float e = __expf(0.125f * (sW[h][m] - mx));  // 1/sqrt(64)
                    sW[h][m] = e;
                    sum += e;
                }
                #pragma unroll
                for (int o = 16; o; o >>= 1) sum += __shfl_xor_sync(0xffffffffu, sum, o);
                const float inv = 1.f / sum;
                for (int m = lane; m < mEnd; m += 32) sW[h][m] *= inv;
            }
        } else {
            const float u = 1.f / (float)Ln;
            for (int m = t; m < Ln; m += 512) {
                sW[0][m] = u; sW[1][m] = u; sW[2][m] = u; sW[3][m] = u;
            }
        }
        __syncthreads();

        float4 acc = make_float4(0.f, 0.f, 0.f, 0.f);
        #pragma unroll 2
        for (int m0 = 0; m0 < mEnd; m0 += 8) {
            const int m = m0 + msub;
            if (m < mEnd) {
                const float  a   = sW[head][m];
                const size_t off = (rowBase + (size_t)m) * 64 + qd;
                const float4 x = tV[off];
                const float4 y = dV[off];
                const float4 v = Vc4[(size_t)(b * Ln + m) * 64 + qd];
                acc.x += a * (x.x + y.x + v.x);
                acc.y += a * (x.y + y.y + v.y);
                acc.z += a * (x.z + y.z + v.z);
                acc.w += a * (x.w + y.w + v.w);
            }
        }
        sRed[msub][qd] = acc;
        __syncthreads();
        if (msub == 0) {
            float4 o = sRed[0][qd];
            #pragma unroll
            for (int r = 1; r < 8; ++r) {
                const float4 rv = sRed[r][qd];
                o.x += rv.x; o.y += rv.y; o.z += rv.z; o.w += rv.w;
            }
            out[(size_t)(b * Ln + l) * 64 + qd] = o;
        }
        __syncthreads();
    }
}

// ---------------------------------------------------------------------------
extern "C" void kernel_launch(void* const* d_in, const int* in_sizes, int n_in,
                              void* d_out, int out_size)
{
    const float4* queries = (const float4*)d_in[0];
    const float4* keys    = (const float4*)d_in[1];
    const float4* tK      = (const float4*)d_in[2];
    const float4* tV      = (const float4*)d_in[3];
    const float4* dK      = (const float4*)d_in[4];
    const float4* dV      = (const float4*)d_in[5];
    const float4* apK     = (const float4*)d_in[6];
    const float4* apV     = (const float4*)d_in[7];
    const float4* Qw      = (const float4*)d_in[8];
    const float* Qb       = (const float*)d_in[9];
    const float4* Kw      = (const float4*)d_in[10];
    const float* Kb       = (const float*)d_in[11];
    const float4* Vw      = (const float4*)d_in[12];
    const float* Vb       = (const float*)d_in[13];
    const unsigned char* time_mask = (const unsigned char*)d_in[14];

    proj_strip<<<148, 512>>>(queries, keys, apK, apV,
                             Qw, Qb, Kw, Kb, Vw, Vb);

    cudaLaunchConfig_t cfg = {};
    cfg.gridDim  = dim3(444, 1, 1);
    cfg.blockDim = dim3(512, 1, 1);
    cfg.dynamicSmemBytes = 0;
    cfg.stream = 0;
    cudaLaunchAttribute attrs[1];
    attrs[0].id = cudaLaunchAttributeProgrammaticStreamSerialization;
    attrs[0].val.programmaticStreamSerializationAllowed = 1;
    cfg.attrs = attrs;
    cfg.numAttrs = 1;
    cudaLaunchKernelEx(&cfg, attn_kernel, tK, tV, dK, dV, time_mask,
                       (float4*)d_out);
}